// round 15
// baseline (speedup 1.0000x reference)
#include <cuda_runtime.h>
#include <cuda_fp16.h>
#include <math.h>

#define Npts 32768
#define CCH 128
#define KNN 16
#define GDIM 20
#define NCELL 8000
#define CS 5.0f
#define CINV 0.2f
#define FLTMAX 3.402823466e38f

__device__ int    d_cc[NCELL];
__device__ int    d_cs[NCELL + 1];
__device__ int    d_cur[NCELL];
__device__ float4 d_sorted[Npts];
__device__ int    d_knn[Npts * KNN];
__device__ int    d_nflag;
__device__ int    d_flag[Npts];
__device__ __align__(16) float d_Wpk0[3*CCH], d_bk0[CCH], d_Wpv0[3*CCH], d_bv0[CCH];
__device__ __align__(16) float d_Wpk1[3*CCH], d_bk1[CCH], d_Wpv1[3*CCH], d_bv1[CCH];
__device__ __align__(16) __half d_Q[Npts*CCH], d_FK[Npts*CCH], d_FV[Npts*CCH];
__device__ float d_O0[Npts*CCH], d_O1[Npts*CCH], d_H[Npts*CCH], d_H1[Npts*CCH];
__device__ __align__(16) unsigned short d_wbh[7*16384];

__device__ __forceinline__ int cellof(float x){ int c=(int)(x*CINV); return min(GDIM-1,max(0,c)); }

#define CPA16(dst,src)  asm volatile("cp.async.cg.shared.global [%0],[%1],16;"::"r"(dst),"l"(src))
#define CPA_COMMIT()    asm volatile("cp.async.commit_group;")
#define CPA_WAIT(n)     asm volatile("cp.async.wait_group %0;"::"n"(n):"memory")
__device__ __forceinline__ unsigned s2u(const void* p){
    unsigned a; asm("{.reg .u64 t; cvta.to.shared.u64 t,%1; cvt.u32.u64 %0,t;}":"=r"(a):"l"(p)); return a; }
__device__ __forceinline__ void ldsm4(unsigned* r, unsigned addr){
    asm volatile("ldmatrix.sync.aligned.m8n8.x4.shared.b16 {%0,%1,%2,%3},[%4];"
        :"=r"(r[0]),"=r"(r[1]),"=r"(r[2]),"=r"(r[3]):"r"(addr));
}
__device__ __forceinline__ void mma16816h(float* d,const unsigned* a,unsigned b0,unsigned b1){
    asm volatile("mma.sync.aligned.m16n8k16.row.col.f32.f16.f16.f32 "
        "{%0,%1,%2,%3},{%4,%5,%6,%7},{%8,%9},{%0,%1,%2,%3};"
        :"+f"(d[0]),"+f"(d[1]),"+f"(d[2]),"+f"(d[3])
        :"r"(a[0]),"r"(a[1]),"r"(a[2]),"r"(a[3]),"r"(b0),"r"(b1));
}

// ---------------- grid build + knn ----------------
__global__ void hist_k(const float4* __restrict__ co){
    int i=blockIdx.x*256+threadIdx.x; if(i>=Npts)return; float4 c=co[i];
    atomicAdd(&d_cc[(cellof(c.w)*GDIM+cellof(c.z))*GDIM+cellof(c.y)],1);
}
__global__ void scan_k(){
    __shared__ int s[1024]; int t=threadIdx.x;
    int b=t*8, c[8], sum=0;
    if(t<1000){
#pragma unroll
        for(int i=0;i<8;++i){ c[i]=d_cc[b+i]; sum+=c[i]; }
    }
    s[t]=sum; __syncthreads();
    for(int o=1;o<1024;o<<=1){ int v=(t>=o)?s[t-o]:0; __syncthreads(); s[t]+=v; __syncthreads(); }
    int run=s[t]-sum;
    if(t<1000){
#pragma unroll
        for(int i=0;i<8;++i){ d_cs[b+i]=run; d_cur[b+i]=run; run+=c[i]; }
    }
    if(t==1023)d_cs[NCELL]=s[1023];
}
__global__ void scat_k(const float4* __restrict__ co){
    int i=blockIdx.x*256+threadIdx.x; if(i>=Npts)return; float4 c=co[i];
    int id=(cellof(c.w)*GDIM+cellof(c.z))*GDIM+cellof(c.y);
    d_sorted[atomicAdd(&d_cur[id],1)]=make_float4(c.y,c.z,c.w,__int_as_float(i));
}

__device__ __forceinline__ void ins1(float d,int idx,float(&ds)[KNN],int(&nb)[KNN]){
    if(d<ds[KNN-1]){ float cd=d; int ci=idx;
#pragma unroll
        for(int u=0;u<KNN;++u) if(cd<ds[u]){float td=ds[u];ds[u]=cd;cd=td;int ti=nb[u];nb[u]=ci;ci=ti;}
    }
}
__device__ __forceinline__ void seg(int s_,int e,int st,float qx,float qy,float qz,float(&ds)[KNN],int(&nb)[KNN]){
    int t=s_+st;
    for(; t+6<e; t+=8){
        float4 p0=d_sorted[t],p1=d_sorted[t+2],p2=d_sorted[t+4],p3=d_sorted[t+6];
        float x0=qx-p0.x,y0=qy-p0.y,z0=qz-p0.z; float d0=fmaf(x0,x0,fmaf(y0,y0,z0*z0));
        float x1=qx-p1.x,y1=qy-p1.y,z1=qz-p1.z; float d1=fmaf(x1,x1,fmaf(y1,y1,z1*z1));
        float x2=qx-p2.x,y2=qy-p2.y,z2=qz-p2.z; float d2=fmaf(x2,x2,fmaf(y2,y2,z2*z2));
        float x3=qx-p3.x,y3=qy-p3.y,z3=qz-p3.z; float d3=fmaf(x3,x3,fmaf(y3,y3,z3*z3));
        ins1(d0,__float_as_int(p0.w),ds,nb);
        ins1(d1,__float_as_int(p1.w),ds,nb);
        ins1(d2,__float_as_int(p2.w),ds,nb);
        ins1(d3,__float_as_int(p3.w),ds,nb);
    }
    for(;t<e;t+=2){ float4 p=d_sorted[t];
        float dx=qx-p.x,dy=qy-p.y,dz=qz-p.z;
        ins1(fmaf(dx,dx,fmaf(dy,dy,dz*dz)),__float_as_int(p.w),ds,nb);
    }
}
__global__ void knn_k(){
    int qt=blockIdx.x*512+threadIdx.x;
    int i=qt>>1, st=qt&1;
    if(i>=Npts)return;
    float4 q=d_sorted[i]; float qx=q.x,qy=q.y,qz=q.z; int qi=__float_as_int(q.w);
    int cx=cellof(qx),cy=cellof(qy),cz=cellof(qz);
    float ds[KNN]; int nb[KNN];
#pragma unroll
    for(int u=0;u<KNN;++u){ds[u]=FLTMAX;nb[u]=0;}
    int x0a=max(cx-1,0),x1a=min(cx+1,GDIM-1),y0a=max(cy-1,0),y1a=min(cy+1,GDIM-1),z0a=max(cz-1,0),z1a=min(cz+1,GDIM-1);
    int x0b=max(cx-2,0),x1b=min(cx+2,GDIM-1),y0b=max(cy-2,0),y1b=min(cy+2,GDIM-1),z0b=max(cz-2,0),z1b=min(cz+2,GDIM-1);
    for(int zz=z0a;zz<=z1a;++zz)for(int yy=y0a;yy<=y1a;++yy){
        int rb=(zz*GDIM+yy)*GDIM; seg(d_cs[rb+x0a],d_cs[rb+x1a+1],st,qx,qy,qz,ds,nb); }
    for(int zz=z0b;zz<=z1b;++zz){
        float tz=fmaxf(fmaxf(zz*CS-qz,qz-(zz+1)*CS),0.f);
        for(int yy=y0b;yy<=y1b;++yy){
            float ty=fmaxf(fmaxf(yy*CS-qy,qy-(yy+1)*CS),0.f); float tyz=ty*ty+tz*tz;
            int rb=(zz*GDIM+yy)*GDIM;
            bool inr=(zz>=z0a&&zz<=z1a&&yy>=y0a&&yy<=y1a);
            if(!inr){ if(tyz<ds[KNN-1]) seg(d_cs[rb+x0b],d_cs[rb+x1b+1],st,qx,qy,qz,ds,nb); }
            else{
                if(x0b<x0a){ float tx=qx-x0a*CS; if(tyz+tx*tx<ds[KNN-1]) seg(d_cs[rb+x0b],d_cs[rb+x0a],st,qx,qy,qz,ds,nb);}
                if(x1b>x1a){ float tx=(x1a+1)*CS-qx; if(tyz+tx*tx<ds[KNN-1]) seg(d_cs[rb+x1a+1],d_cs[rb+x1b+1],st,qx,qy,qz,ds,nb);}
            }
        }}
    float mx=0.f; int LI[KNN];
#pragma unroll
    for(int u=0;u<KNN;++u){
        float pv=__shfl_xor_sync(0xffffffffu,ds[KNN-1-u],1);
        int   pi=__shfl_xor_sync(0xffffffffu,nb[KNN-1-u],1);
        float lv; int li;
        if(ds[u]<=pv){lv=ds[u];li=nb[u];}else{lv=pv;li=pi;}
        mx=fmaxf(mx,lv); LI[u]=li;
    }
    if(st==0){
        float Rg=2.f*CS-0.01f;
        if(mx<=Rg*Rg){
#pragma unroll
            for(int u=0;u<KNN;++u)d_knn[qi*KNN+u]=LI[u];
        }else d_flag[atomicAdd(&d_nflag,1)]=qi;
    }
}
__global__ void knn_fb(const float4* __restrict__ co){
    __shared__ float sd[8][512]; __shared__ int si[8][512];
    int wl=threadIdx.x>>5,ln=threadIdx.x&31;
    int gw=blockIdx.x*8+wl, tot=gridDim.x*8, nf=d_nflag;
    for(int w=gw;w<nf;w+=tot){
        int qi=d_flag[w]; float4 qc=co[qi]; float qx=qc.y,qy=qc.z,qz=qc.w;
        float ds[KNN]; int nb[KNN];
#pragma unroll
        for(int u=0;u<KNN;++u){ds[u]=FLTMAX;nb[u]=0;}
        for(int t=ln;t<Npts;t+=32){ float4 p=co[t];
            float dx=qx-p.y,dy=qy-p.z,dz=qz-p.w;
            ins1(fmaf(dx,dx,fmaf(dy,dy,dz*dz)),t,ds,nb);
        }
#pragma unroll
        for(int u=0;u<KNN;++u){sd[wl][ln*16+u]=ds[u];si[wl][ln*16+u]=nb[u];}
        __syncwarp();
        if(ln==0) for(int r=0;r<KNN;++r){
            float bm=FLTMAX;int bp=0;
            for(int t=0;t<512;++t) if(sd[wl][t]<bm){bm=sd[wl][t];bp=t;}
            d_knn[qi*KNN+r]=si[wl][bp]; sd[wl][bp]=FLTMAX; }
        __syncwarp();
    }
}

__global__ void prep_w(const float* pw,const float* pb,const float* p1w,const float* p1b,
                       const float* kw0,const float* kb0,const float* vw0,const float* vb0,
                       const float* kw1,const float* kb1,const float* vw1,const float* vb1){
    int c=threadIdx.x;
    for(int m=0;m<3;++m){ float a=0,b=0,e=0,f=0;
        for(int t=0;t<CCH;++t){ a=fmaf(pw[m*CCH+t],kw0[t*CCH+c],a); b=fmaf(pw[m*CCH+t],vw0[t*CCH+c],b);
            e=fmaf(p1w[m*CCH+t],kw1[t*CCH+c],e); f=fmaf(p1w[m*CCH+t],vw1[t*CCH+c],f); }
        d_Wpk0[m*CCH+c]=a; d_Wpv0[m*CCH+c]=b; d_Wpk1[m*CCH+c]=e; d_Wpv1[m*CCH+c]=f; }
    float a=0,b=0,e=0,f=0;
    for(int t=0;t<CCH;++t){ a=fmaf(pb[t],kw0[t*CCH+c],a); b=fmaf(pb[t],vw0[t*CCH+c],b);
        e=fmaf(p1b[t],kw1[t*CCH+c],e); f=fmaf(p1b[t],vw1[t*CCH+c],f); }
    d_bk0[c]=a+kb0[c]; d_bv0[c]=b+vb0[c]; d_bk1[c]=e+kb1[c]; d_bv1[c]=f+vb1[c];
}

__global__ void prep_wb(const float* w0,const float* w1,const float* w2,const float* w3,
                        const float* w4,const float* w5,const float* w6){
    int m=blockIdx.x>>4;
    const float* W=(m==0)?w0:(m==1)?w1:(m==2)?w2:(m==3)?w3:(m==4)?w4:(m==5)?w5:w6;
    int q=(blockIdx.x&15)*256+threadIdx.x;
    int n=q>>5, k0=(q&31)*4;
    union{__half b[4]; unsigned long long u;} H;
#pragma unroll
    for(int i=0;i<4;++i) H.b[i]=__float2half_rn(W[(k0+i)*128+n]);
    *(unsigned long long*)((char*)d_wbh + m*32768 + n*256 + k0*2)=H.u;
}

// ---- fp16 HMMA GEMM ----
#define APAD 272
#define OFF_A  0
#define OFF_B0 (128*APAD)
#define OFF_B1 (2*128*APAD)
#define GM_SMEM (3*128*APAD)

__global__ void __launch_bounds__(256,2)
gemmM_k(const float* __restrict__ A,
        const unsigned short* __restrict__ wh0,const unsigned short* __restrict__ wh1,
        const unsigned short* __restrict__ wh2,
        const float* __restrict__ bi0,const float* __restrict__ bi1,const float* __restrict__ bi2,
        void* __restrict__ C0,void* __restrict__ C1,void* __restrict__ C2,int nmat,int h16){
    extern __shared__ __align__(16) char sm[];
    unsigned sb=s2u(sm);
    int tid=threadIdx.x, wid=tid>>5, lane=tid&31, row0=blockIdx.x*128;
    {
        const unsigned short* W=wh0;
        for(int i=tid;i<2048;i+=256){ int r=i>>4, ch=(i&15)*16;
            CPA16(sb+OFF_B0+r*APAD+ch,(const char*)W+r*256+ch); }
        CPA_COMMIT();
    }
    {
        int row=tid>>1, half=(tid&1)*64;
        const float4* Ar=(const float4*)(A+(size_t)(row0+row)*128+half);
        char* dh=sm+OFF_A+row*APAD+half*2;
#pragma unroll
        for(int c4=0;c4<16;++c4){
            float4 v=Ar[c4];
            union{__half b[4]; unsigned long long u;} H;
            H.b[0]=__float2half_rn(v.x); H.b[1]=__float2half_rn(v.y);
            H.b[2]=__float2half_rn(v.z); H.b[3]=__float2half_rn(v.w);
            *(unsigned long long*)(dh+c4*8)=H.u;
        }
    }
    int wm=wid>>1, wn=wid&1;
    unsigned arow=sb+OFF_A+(wm*32+(lane&15))*APAD+(lane>>4)*16;
    for(int m=0;m<nmat;++m){
        if(m+1<nmat){
            const unsigned short* W=(m+1==1)?wh1:wh2;
            unsigned bo=((m+1)&1)?OFF_B1:OFF_B0;
            for(int i=tid;i<2048;i+=256){ int r=i>>4, ch=(i&15)*16;
                CPA16(sb+bo+r*APAD+ch,(const char*)W+r*256+ch); }
            CPA_COMMIT();
            CPA_WAIT(1);
        }else CPA_WAIT(0);
        __syncthreads();

        const float* bi=(m==0)?bi0:((m==1)?bi1:bi2);
        void* C=(m==0)?C0:((m==1)?C1:C2);
        unsigned brow=sb+((m&1)?OFF_B1:OFF_B0)+(wn*64+(lane&15))*APAD+(lane>>4)*16;

        float acc[2][8][4];
#pragma unroll
        for(int mt=0;mt<2;++mt)
#pragma unroll
            for(int nt=0;nt<8;++nt)
#pragma unroll
                for(int e=0;e<4;++e)acc[mt][nt][e]=0.f;
#pragma unroll
        for(int ks=0;ks<8;++ks){
            unsigned a0[4],a1[4],bg[4][4];
            unsigned kof=ks*32;
            ldsm4(a0,arow+kof);
            ldsm4(a1,arow+16*APAD+kof);
#pragma unroll
            for(int g=0;g<4;++g) ldsm4(bg[g],brow+g*16*APAD+kof);
#pragma unroll
            for(int mt=0;mt<2;++mt){
                const unsigned* af=mt?a1:a0;
#pragma unroll
                for(int nt=0;nt<8;++nt)
                    mma16816h(acc[mt][nt],af,bg[nt>>1][nt&1],bg[nt>>1][(nt&1)+2]);
            }
        }
#pragma unroll
        for(int mt=0;mt<2;++mt){
            int r0=row0+wm*32+mt*16+(lane>>2);
#pragma unroll
            for(int nt=0;nt<8;++nt){
                int n=wn*64+nt*8+(lane&3)*2;
                float2 bb=make_float2(0.f,0.f);
                if(bi) bb=*(const float2*)(bi+n);
                float2 o0; o0.x=acc[mt][nt][0]+bb.x; o0.y=acc[mt][nt][1]+bb.y;
                float2 o1; o1.x=acc[mt][nt][2]+bb.x; o1.y=acc[mt][nt][3]+bb.y;
                if(h16){
                    __half2* Ch=(__half2*)C;
                    Ch[(size_t)r0*64+(n>>1)]=__floats2half2_rn(o0.x,o0.y);
                    Ch[(size_t)(r0+8)*64+(n>>1)]=__floats2half2_rn(o1.x,o1.y);
                }else{
                    float* Cf=(float*)C;
                    *(float2*)(Cf+(size_t)r0*128+n)=o0;
                    *(float2*)(Cf+(size_t)(r0+8)*128+n)=o1;
                }
            }
        }
        __syncthreads();
    }
}

// ---------------- attention: two-phase, register-prefetched, scalar geo ----------------
__device__ __forceinline__ float4 up4(uint2 u){
    float2 a=__half22float2(*(__half2*)&u.x), b=__half22float2(*(__half2*)&u.y);
    return make_float4(a.x,a.y,b.x,b.y);
}
__device__ __forceinline__ float wredu(float v){
#pragma unroll
    for(int o=16;o;o>>=1)v+=__shfl_xor_sync(0xffffffffu,v,o);
    return v;
}
__global__ void attn_k(const __half* __restrict__ Qh,const __half* __restrict__ FKh,
                       const __half* __restrict__ FVh,const float4* __restrict__ co,
                       float4* __restrict__ Out4,int layer){
    int n=(blockIdx.x*blockDim.x+threadIdx.x)>>5, ln=threadIdx.x&31;
    if(n>=Npts)return;
    const float4* Wk=(const float4*)(layer?d_Wpk1:d_Wpk0);
    const float4* Bk=(const float4*)(layer?d_bk1:d_bk0);
    float4 q=up4(((const uint2*)(Qh+(size_t)n*128))[ln]);
    float ax,ay,az,ab;
    {
        float4 wkx=Wk[ln],wky=Wk[32+ln],wkz=Wk[64+ln],bk=Bk[ln];
        ax=wredu(fmaf(wkx.w,q.w,fmaf(wkx.z,q.z,fmaf(wkx.y,q.y,wkx.x*q.x))));
        ay=wredu(fmaf(wky.w,q.w,fmaf(wky.z,q.z,fmaf(wky.y,q.y,wky.x*q.x))));
        az=wredu(fmaf(wkz.w,q.w,fmaf(wkz.z,q.z,fmaf(wkz.y,q.y,wkz.x*q.x))));
        ab=wredu(fmaf(bk.w,q.w,fmaf(bk.z,q.z,fmaf(bk.y,q.y,bk.x*q.x))));
    }
    float4 qc=co[n];
    int jj[KNN];
#pragma unroll
    for(int k=0;k<KNN;++k)jj[k]=d_knn[n*KNN+k];
    // Phase A: prefetch all FK rows, then 16 independent score reductions
    uint2 ur[KNN];
#pragma unroll
    for(int k=0;k<KNN;++k) ur[k]=((const uint2*)(FKh+(size_t)jj[k]*128))[ln];
    float sc[KNN];
#pragma unroll
    for(int k=0;k<KNN;++k){
        float4 fk=up4(ur[k]);
        float p=fmaf(fk.w,q.w,fmaf(fk.z,q.z,fmaf(fk.y,q.y,fk.x*q.x)));
#pragma unroll
        for(int o=16;o;o>>=1)p+=__shfl_xor_sync(0xffffffffu,p,o);
        float4 pj=co[jj[k]];
        float dx=qc.y-pj.y,dy=qc.z-pj.z,dz=qc.w-pj.w;
        sc[k]=(p+fmaf(dz,az,fmaf(dy,ay,fmaf(dx,ax,ab))))*0.08838834764831845f;
    }
    // Prefetch FV rows (reuse ur) while computing softmax weights
#pragma unroll
    for(int k=0;k<KNN;++k) ur[k]=((const uint2*)(FVh+(size_t)jj[k]*128))[ln];
    float m=sc[0];
#pragma unroll
    for(int k=1;k<KNN;++k)m=fmaxf(m,sc[k]);
    float sum=0.f;
#pragma unroll
    for(int k=0;k<KNN;++k){ sc[k]=__expf(sc[k]-m); sum+=sc[k]; }
    // Phase B: weighted accumulation
    float Sx=0.f,Sy=0.f,Sz=0.f;
    float4 ac=make_float4(0.f,0.f,0.f,0.f);
#pragma unroll
    for(int k=0;k<KNN;++k){
        float a=sc[k];
        float4 pj=co[jj[k]];
        float dx=qc.y-pj.y,dy=qc.z-pj.z,dz=qc.w-pj.w;
        Sx=fmaf(a,dx,Sx); Sy=fmaf(a,dy,Sy); Sz=fmaf(a,dz,Sz);
        float4 fv=up4(ur[k]);
        ac.x=fmaf(a,fv.x,ac.x); ac.y=fmaf(a,fv.y,ac.y);
        ac.z=fmaf(a,fv.z,ac.z); ac.w=fmaf(a,fv.w,ac.w);
    }
    const float4* Wv=(const float4*)(layer?d_Wpv1:d_Wpv0);
    const float4* Bv=(const float4*)(layer?d_bv1:d_bv0);
    float4 wvx=Wv[ln],wvy=Wv[32+ln],wvz=Wv[64+ln],bv=Bv[ln];
    float inv=1.f/sum;
    float sx=Sx*inv, sy=Sy*inv, sz=Sz*inv;
    float4 o;
    o.x=fmaf(ac.x,inv,fmaf(sx,wvx.x,fmaf(sy,wvy.x,fmaf(sz,wvz.x,bv.x))));
    o.y=fmaf(ac.y,inv,fmaf(sx,wvx.y,fmaf(sy,wvy.y,fmaf(sz,wvz.y,bv.y))));
    o.z=fmaf(ac.z,inv,fmaf(sx,wvx.z,fmaf(sy,wvy.z,fmaf(sz,wvz.z,bv.z))));
    o.w=fmaf(ac.w,inv,fmaf(sx,wvx.w,fmaf(sy,wvy.w,fmaf(sz,wvz.w,bv.w))));
    Out4[n*32+ln]=o;
}

__global__ void ln_k(const float4* __restrict__ X4,const float4* __restrict__ Y4,
                     const float4* __restrict__ g4,const float4* __restrict__ b4,
                     float4* __restrict__ out4){
    int n=(blockIdx.x*blockDim.x+threadIdx.x)>>5, ln=threadIdx.x&31;
    if(n>=Npts)return;
    float4 x=X4[n*32+ln], y=Y4[n*32+ln];
    float4 v; v.x=x.x+y.x; v.y=x.y+y.y; v.z=x.z+y.z; v.w=x.w+y.w;
    float s=v.x+v.y+v.z+v.w;
#pragma unroll
    for(int o=16;o;o>>=1)s+=__shfl_xor_sync(0xffffffffu,s,o);
    float mu=s*(1.f/128.f);
    float dx=v.x-mu,dy=v.y-mu,dz=v.z-mu,dw=v.w-mu;
    float vs=fmaf(dx,dx,fmaf(dy,dy,fmaf(dz,dz,dw*dw)));
#pragma unroll
    for(int o=16;o;o>>=1)vs+=__shfl_xor_sync(0xffffffffu,vs,o);
    float inv=rsqrtf(vs*(1.f/128.f)+128.f);
    float4 g=g4[ln],b=b4[ln],o;
    o.x=fmaf(dx*inv,g.x,b.x); o.y=fmaf(dy*inv,g.y,b.y);
    o.z=fmaf(dz*inv,g.z,b.z); o.w=fmaf(dw*inv,g.w,b.w);
    out4[n*32+ln]=o;
}

extern "C" void kernel_launch(void* const* d_in,const int* in_sizes,int n_in,
                              void* d_out,int out_size){
    const float4* co=(const float4*)d_in[0];
    const float* feats=(const float*)d_in[1];
    const float* pw=(const float*)d_in[2];  const float* pb=(const float*)d_in[3];
    const float* p1w=(const float*)d_in[4]; const float* p1b=(const float*)d_in[5];
    const float* qw0=(const float*)d_in[6]; const float* qb0=(const float*)d_in[7];
    const float* kw0=(const float*)d_in[8]; const float* kb0=(const float*)d_in[9];
    const float* vw0=(const float*)d_in[10];const float* vb0=(const float*)d_in[11];
    const float* qw1=(const float*)d_in[12];const float* qb1=(const float*)d_in[13];
    const float* kw1=(const float*)d_in[14];const float* kb1=(const float*)d_in[15];
    const float* vw1=(const float*)d_in[16];const float* vb1=(const float*)d_in[17];
    const float* lw=(const float*)d_in[18]; const float* lb=(const float*)d_in[19];
    const float* g0=(const float*)d_in[20]; const float* be0=(const float*)d_in[21];
    const float* g1=(const float*)d_in[22]; const float* be1=(const float*)d_in[23];
    float* out=(float*)d_out;

    __half *Q,*FK,*FV; float *O0,*O1,*H,*H1; unsigned short *WH;
    int *CC,*NF;
    cudaGetSymbolAddress((void**)&Q,d_Q);   cudaGetSymbolAddress((void**)&FK,d_FK);
    cudaGetSymbolAddress((void**)&FV,d_FV); cudaGetSymbolAddress((void**)&O0,d_O0);
    cudaGetSymbolAddress((void**)&O1,d_O1); cudaGetSymbolAddress((void**)&H,d_H);
    cudaGetSymbolAddress((void**)&H1,d_H1);
    cudaGetSymbolAddress((void**)&WH,d_wbh);
    cudaGetSymbolAddress((void**)&CC,d_cc); cudaGetSymbolAddress((void**)&NF,d_nflag);
    const float* nf=0;
    cudaFuncSetAttribute(gemmM_k,cudaFuncAttributeMaxDynamicSharedMemorySize,GM_SMEM);
#define WQ(i) (WH+(i)*16384)

    cudaMemsetAsync(CC,0,NCELL*sizeof(int),(cudaStream_t)0);
    cudaMemsetAsync(NF,0,sizeof(int),(cudaStream_t)0);
    hist_k<<<128,256>>>(co);
    scan_k<<<1,1024>>>();
    scat_k<<<128,256>>>(co);
    knn_k<<<128,512>>>();                    // profiled slot
    knn_fb<<<64,256>>>(co);
    prep_wb<<<112,256>>>(qw0,kw0,vw0,qw1,kw1,vw1,lw);
    gemmM_k<<<256,256,GM_SMEM>>>(feats,WQ(0),WQ(1),WQ(2),qb0,nf,nf,Q,FK,FV,3,1);
    prep_w<<<1,128>>>(pw,pb,p1w,p1b,kw0,kb0,vw0,vb0,kw1,kb1,vw1,vb1);
    attn_k<<<4096,256>>>(Q,FK,FV,co,(float4*)O0,0);
    gemmM_k<<<256,256,GM_SMEM>>>(O0,WQ(3),WQ(4),WQ(5),qb1,nf,nf,Q,FK,FV,3,1);
    attn_k<<<4096,256>>>(Q,FK,FV,co,(float4*)O1,1);
    ln_k<<<4096,256>>>((const float4*)feats,(const float4*)O1,(const float4*)g0,(const float4*)be0,(float4*)H);
    gemmM_k<<<256,256,GM_SMEM>>>(H,WQ(6),WQ(6),WQ(6),lb,nf,nf,H1,(float*)0,(float*)0,1,0);
    ln_k<<<4096,256>>>((const float4*)H,(const float4*)H1,(const float4*)g1,(const float4*)be1,(float4*)out);
}

// round 16
// speedup vs baseline: 1.4573x; 1.4573x over previous
#include <cuda_runtime.h>
#include <cuda_fp16.h>
#include <math.h>

#define Npts 32768
#define CCH 128
#define KNN 16
#define GDIM 20
#define NCELL 8000
#define CS 5.0f
#define CINV 0.2f
#define FLTMAX 3.402823466e38f

__device__ int    d_cc[NCELL];
__device__ int    d_cs[NCELL + 1];
__device__ int    d_cur[NCELL];
__device__ float4 d_sorted[Npts];
__device__ int    d_knn[Npts * KNN];
__device__ int    d_nflag;
__device__ int    d_flag[Npts];
__device__ __align__(16) float d_Wpk0[3*CCH], d_bk0[CCH], d_Wpv0[3*CCH], d_bv0[CCH];
__device__ __align__(16) float d_Wpk1[3*CCH], d_bk1[CCH], d_Wpv1[3*CCH], d_bv1[CCH];
__device__ __align__(16) __half d_Q[Npts*CCH], d_FK[Npts*CCH], d_FV[Npts*CCH];
__device__ float d_O0[Npts*CCH], d_O1[Npts*CCH], d_H[Npts*CCH], d_H1[Npts*CCH];
__device__ __align__(16) unsigned short d_wbh[7*16384];

__device__ __forceinline__ int cellof(float x){ int c=(int)(x*CINV); return min(GDIM-1,max(0,c)); }

#define CPA16(dst,src)  asm volatile("cp.async.cg.shared.global [%0],[%1],16;"::"r"(dst),"l"(src))
#define CPA_COMMIT()    asm volatile("cp.async.commit_group;")
#define CPA_WAIT(n)     asm volatile("cp.async.wait_group %0;"::"n"(n):"memory")
__device__ __forceinline__ unsigned s2u(const void* p){
    unsigned a; asm("{.reg .u64 t; cvta.to.shared.u64 t,%1; cvt.u32.u64 %0,t;}":"=r"(a):"l"(p)); return a; }
__device__ __forceinline__ void ldsm4(unsigned* r, unsigned addr){
    asm volatile("ldmatrix.sync.aligned.m8n8.x4.shared.b16 {%0,%1,%2,%3},[%4];"
        :"=r"(r[0]),"=r"(r[1]),"=r"(r[2]),"=r"(r[3]):"r"(addr));
}
__device__ __forceinline__ void mma16816h(float* d,const unsigned* a,unsigned b0,unsigned b1){
    asm volatile("mma.sync.aligned.m16n8k16.row.col.f32.f16.f16.f32 "
        "{%0,%1,%2,%3},{%4,%5,%6,%7},{%8,%9},{%0,%1,%2,%3};"
        :"+f"(d[0]),"+f"(d[1]),"+f"(d[2]),"+f"(d[3])
        :"r"(a[0]),"r"(a[1]),"r"(a[2]),"r"(a[3]),"r"(b0),"r"(b1));
}

// ---------------- grid build + knn ----------------
__global__ void hist_k(const float4* __restrict__ co){
    int i=blockIdx.x*256+threadIdx.x; if(i>=Npts)return; float4 c=co[i];
    atomicAdd(&d_cc[(cellof(c.w)*GDIM+cellof(c.z))*GDIM+cellof(c.y)],1);
}
__global__ void scan_k(){
    __shared__ int s[1024]; int t=threadIdx.x;
    int b=t*8, c[8], sum=0;
    if(t<1000){
#pragma unroll
        for(int i=0;i<8;++i){ c[i]=d_cc[b+i]; sum+=c[i]; }
    }
    s[t]=sum; __syncthreads();
    for(int o=1;o<1024;o<<=1){ int v=(t>=o)?s[t-o]:0; __syncthreads(); s[t]+=v; __syncthreads(); }
    int run=s[t]-sum;
    if(t<1000){
#pragma unroll
        for(int i=0;i<8;++i){ d_cs[b+i]=run; d_cur[b+i]=run; run+=c[i]; }
    }
    if(t==1023)d_cs[NCELL]=s[1023];
}
__global__ void scat_k(const float4* __restrict__ co){
    int i=blockIdx.x*256+threadIdx.x; if(i>=Npts)return; float4 c=co[i];
    int id=(cellof(c.w)*GDIM+cellof(c.z))*GDIM+cellof(c.y);
    d_sorted[atomicAdd(&d_cur[id],1)]=make_float4(c.y,c.z,c.w,__int_as_float(i));
}

__device__ __forceinline__ void ins1(float d,int idx,float(&ds)[KNN],int(&nb)[KNN]){
    if(d<ds[KNN-1]){ float cd=d; int ci=idx;
#pragma unroll
        for(int u=0;u<KNN;++u) if(cd<ds[u]){float td=ds[u];ds[u]=cd;cd=td;int ti=nb[u];nb[u]=ci;ci=ti;}
    }
}
__device__ __forceinline__ void seg(int s_,int e,int st,float qx,float qy,float qz,float(&ds)[KNN],int(&nb)[KNN]){
    int t=s_+st;
    for(; t+6<e; t+=8){
        float4 p0=d_sorted[t],p1=d_sorted[t+2],p2=d_sorted[t+4],p3=d_sorted[t+6];
        float x0=qx-p0.x,y0=qy-p0.y,z0=qz-p0.z; float d0=fmaf(x0,x0,fmaf(y0,y0,z0*z0));
        float x1=qx-p1.x,y1=qy-p1.y,z1=qz-p1.z; float d1=fmaf(x1,x1,fmaf(y1,y1,z1*z1));
        float x2=qx-p2.x,y2=qy-p2.y,z2=qz-p2.z; float d2=fmaf(x2,x2,fmaf(y2,y2,z2*z2));
        float x3=qx-p3.x,y3=qy-p3.y,z3=qz-p3.z; float d3=fmaf(x3,x3,fmaf(y3,y3,z3*z3));
        ins1(d0,__float_as_int(p0.w),ds,nb);
        ins1(d1,__float_as_int(p1.w),ds,nb);
        ins1(d2,__float_as_int(p2.w),ds,nb);
        ins1(d3,__float_as_int(p3.w),ds,nb);
    }
    for(;t<e;t+=2){ float4 p=d_sorted[t];
        float dx=qx-p.x,dy=qy-p.y,dz=qz-p.z;
        ins1(fmaf(dx,dx,fmaf(dy,dy,dz*dz)),__float_as_int(p.w),ds,nb);
    }
}
__global__ void knn_k(){
    int qt=blockIdx.x*512+threadIdx.x;
    int i=qt>>1, st=qt&1;
    if(i>=Npts)return;
    float4 q=d_sorted[i]; float qx=q.x,qy=q.y,qz=q.z; int qi=__float_as_int(q.w);
    int cx=cellof(qx),cy=cellof(qy),cz=cellof(qz);
    float ds[KNN]; int nb[KNN];
#pragma unroll
    for(int u=0;u<KNN;++u){ds[u]=FLTMAX;nb[u]=0;}
    int x0a=max(cx-1,0),x1a=min(cx+1,GDIM-1),y0a=max(cy-1,0),y1a=min(cy+1,GDIM-1),z0a=max(cz-1,0),z1a=min(cz+1,GDIM-1);
    int x0b=max(cx-2,0),x1b=min(cx+2,GDIM-1),y0b=max(cy-2,0),y1b=min(cy+2,GDIM-1),z0b=max(cz-2,0),z1b=min(cz+2,GDIM-1);
    for(int zz=z0a;zz<=z1a;++zz)for(int yy=y0a;yy<=y1a;++yy){
        int rb=(zz*GDIM+yy)*GDIM; seg(d_cs[rb+x0a],d_cs[rb+x1a+1],st,qx,qy,qz,ds,nb); }
    for(int zz=z0b;zz<=z1b;++zz){
        float tz=fmaxf(fmaxf(zz*CS-qz,qz-(zz+1)*CS),0.f);
        for(int yy=y0b;yy<=y1b;++yy){
            float ty=fmaxf(fmaxf(yy*CS-qy,qy-(yy+1)*CS),0.f); float tyz=ty*ty+tz*tz;
            int rb=(zz*GDIM+yy)*GDIM;
            bool inr=(zz>=z0a&&zz<=z1a&&yy>=y0a&&yy<=y1a);
            if(!inr){ if(tyz<ds[KNN-1]) seg(d_cs[rb+x0b],d_cs[rb+x1b+1],st,qx,qy,qz,ds,nb); }
            else{
                if(x0b<x0a){ float tx=qx-x0a*CS; if(tyz+tx*tx<ds[KNN-1]) seg(d_cs[rb+x0b],d_cs[rb+x0a],st,qx,qy,qz,ds,nb);}
                if(x1b>x1a){ float tx=(x1a+1)*CS-qx; if(tyz+tx*tx<ds[KNN-1]) seg(d_cs[rb+x1a+1],d_cs[rb+x1b+1],st,qx,qy,qz,ds,nb);}
            }
        }}
    float mx=0.f; int LI[KNN];
#pragma unroll
    for(int u=0;u<KNN;++u){
        float pv=__shfl_xor_sync(0xffffffffu,ds[KNN-1-u],1);
        int   pi=__shfl_xor_sync(0xffffffffu,nb[KNN-1-u],1);
        float lv; int li;
        if(ds[u]<=pv){lv=ds[u];li=nb[u];}else{lv=pv;li=pi;}
        mx=fmaxf(mx,lv); LI[u]=li;
    }
    if(st==0){
        float Rg=2.f*CS-0.01f;
        if(mx<=Rg*Rg){
#pragma unroll
            for(int u=0;u<KNN;++u)d_knn[qi*KNN+u]=LI[u];
        }else d_flag[atomicAdd(&d_nflag,1)]=qi;
    }
}
__global__ void knn_fb(const float4* __restrict__ co){
    __shared__ float sd[8][512]; __shared__ int si[8][512];
    int wl=threadIdx.x>>5,ln=threadIdx.x&31;
    int gw=blockIdx.x*8+wl, tot=gridDim.x*8, nf=d_nflag;
    for(int w=gw;w<nf;w+=tot){
        int qi=d_flag[w]; float4 qc=co[qi]; float qx=qc.y,qy=qc.z,qz=qc.w;
        float ds[KNN]; int nb[KNN];
#pragma unroll
        for(int u=0;u<KNN;++u){ds[u]=FLTMAX;nb[u]=0;}
        for(int t=ln;t<Npts;t+=32){ float4 p=co[t];
            float dx=qx-p.y,dy=qy-p.z,dz=qz-p.w;
            ins1(fmaf(dx,dx,fmaf(dy,dy,dz*dz)),t,ds,nb);
        }
#pragma unroll
        for(int u=0;u<KNN;++u){sd[wl][ln*16+u]=ds[u];si[wl][ln*16+u]=nb[u];}
        __syncwarp();
        if(ln==0) for(int r=0;r<KNN;++r){
            float bm=FLTMAX;int bp=0;
            for(int t=0;t<512;++t) if(sd[wl][t]<bm){bm=sd[wl][t];bp=t;}
            d_knn[qi*KNN+r]=si[wl][bp]; sd[wl][bp]=FLTMAX; }
        __syncwarp();
    }
}

__global__ void prep_w(const float* pw,const float* pb,const float* p1w,const float* p1b,
                       const float* kw0,const float* kb0,const float* vw0,const float* vb0,
                       const float* kw1,const float* kb1,const float* vw1,const float* vb1){
    int c=threadIdx.x;
    for(int m=0;m<3;++m){ float a=0,b=0,e=0,f=0;
        for(int t=0;t<CCH;++t){ a=fmaf(pw[m*CCH+t],kw0[t*CCH+c],a); b=fmaf(pw[m*CCH+t],vw0[t*CCH+c],b);
            e=fmaf(p1w[m*CCH+t],kw1[t*CCH+c],e); f=fmaf(p1w[m*CCH+t],vw1[t*CCH+c],f); }
        d_Wpk0[m*CCH+c]=a; d_Wpv0[m*CCH+c]=b; d_Wpk1[m*CCH+c]=e; d_Wpv1[m*CCH+c]=f; }
    float a=0,b=0,e=0,f=0;
    for(int t=0;t<CCH;++t){ a=fmaf(pb[t],kw0[t*CCH+c],a); b=fmaf(pb[t],vw0[t*CCH+c],b);
        e=fmaf(p1b[t],kw1[t*CCH+c],e); f=fmaf(p1b[t],vw1[t*CCH+c],f); }
    d_bk0[c]=a+kb0[c]; d_bv0[c]=b+vb0[c]; d_bk1[c]=e+kb1[c]; d_bv1[c]=f+vb1[c];
}

__global__ void prep_wb(const float* w0,const float* w1,const float* w2,const float* w3,
                        const float* w4,const float* w5,const float* w6){
    int m=blockIdx.x>>4;
    const float* W=(m==0)?w0:(m==1)?w1:(m==2)?w2:(m==3)?w3:(m==4)?w4:(m==5)?w5:w6;
    int q=(blockIdx.x&15)*256+threadIdx.x;
    int n=q>>5, k0=(q&31)*4;
    union{__half b[4]; unsigned long long u;} H;
#pragma unroll
    for(int i=0;i<4;++i) H.b[i]=__float2half_rn(W[(k0+i)*128+n]);
    *(unsigned long long*)((char*)d_wbh + m*32768 + n*256 + k0*2)=H.u;
}

// ---- fp16 HMMA GEMM ----
#define APAD 272
#define OFF_A  0
#define OFF_B0 (128*APAD)
#define OFF_B1 (2*128*APAD)
#define GM_SMEM (3*128*APAD)

__global__ void __launch_bounds__(256,2)
gemmM_k(const float* __restrict__ A,
        const unsigned short* __restrict__ wh0,const unsigned short* __restrict__ wh1,
        const unsigned short* __restrict__ wh2,
        const float* __restrict__ bi0,const float* __restrict__ bi1,const float* __restrict__ bi2,
        void* __restrict__ C0,void* __restrict__ C1,void* __restrict__ C2,int nmat,int h16){
    extern __shared__ __align__(16) char sm[];
    unsigned sb=s2u(sm);
    int tid=threadIdx.x, wid=tid>>5, lane=tid&31, row0=blockIdx.x*128;
    {
        const unsigned short* W=wh0;
        for(int i=tid;i<2048;i+=256){ int r=i>>4, ch=(i&15)*16;
            CPA16(sb+OFF_B0+r*APAD+ch,(const char*)W+r*256+ch); }
        CPA_COMMIT();
    }
    {
        int row=tid>>1, half=(tid&1)*64;
        const float4* Ar=(const float4*)(A+(size_t)(row0+row)*128+half);
        char* dh=sm+OFF_A+row*APAD+half*2;
#pragma unroll
        for(int c4=0;c4<16;++c4){
            float4 v=Ar[c4];
            union{__half b[4]; unsigned long long u;} H;
            H.b[0]=__float2half_rn(v.x); H.b[1]=__float2half_rn(v.y);
            H.b[2]=__float2half_rn(v.z); H.b[3]=__float2half_rn(v.w);
            *(unsigned long long*)(dh+c4*8)=H.u;
        }
    }
    int wm=wid>>1, wn=wid&1;
    unsigned arow=sb+OFF_A+(wm*32+(lane&15))*APAD+(lane>>4)*16;
    for(int m=0;m<nmat;++m){
        if(m+1<nmat){
            const unsigned short* W=(m+1==1)?wh1:wh2;
            unsigned bo=((m+1)&1)?OFF_B1:OFF_B0;
            for(int i=tid;i<2048;i+=256){ int r=i>>4, ch=(i&15)*16;
                CPA16(sb+bo+r*APAD+ch,(const char*)W+r*256+ch); }
            CPA_COMMIT();
            CPA_WAIT(1);
        }else CPA_WAIT(0);
        __syncthreads();

        const float* bi=(m==0)?bi0:((m==1)?bi1:bi2);
        void* C=(m==0)?C0:((m==1)?C1:C2);
        unsigned brow=sb+((m&1)?OFF_B1:OFF_B0)+(wn*64+(lane&15))*APAD+(lane>>4)*16;

        float acc[2][8][4];
#pragma unroll
        for(int mt=0;mt<2;++mt)
#pragma unroll
            for(int nt=0;nt<8;++nt)
#pragma unroll
                for(int e=0;e<4;++e)acc[mt][nt][e]=0.f;
#pragma unroll
        for(int ks=0;ks<8;++ks){
            unsigned a0[4],a1[4],bg[4][4];
            unsigned kof=ks*32;
            ldsm4(a0,arow+kof);
            ldsm4(a1,arow+16*APAD+kof);
#pragma unroll
            for(int g=0;g<4;++g) ldsm4(bg[g],brow+g*16*APAD+kof);
#pragma unroll
            for(int mt=0;mt<2;++mt){
                const unsigned* af=mt?a1:a0;
#pragma unroll
                for(int nt=0;nt<8;++nt)
                    mma16816h(acc[mt][nt],af,bg[nt>>1][nt&1],bg[nt>>1][(nt&1)+2]);
            }
        }
#pragma unroll
        for(int mt=0;mt<2;++mt){
            int r0=row0+wm*32+mt*16+(lane>>2);
#pragma unroll
            for(int nt=0;nt<8;++nt){
                int n=wn*64+nt*8+(lane&3)*2;
                float2 bb=make_float2(0.f,0.f);
                if(bi) bb=*(const float2*)(bi+n);
                float2 o0; o0.x=acc[mt][nt][0]+bb.x; o0.y=acc[mt][nt][1]+bb.y;
                float2 o1; o1.x=acc[mt][nt][2]+bb.x; o1.y=acc[mt][nt][3]+bb.y;
                if(h16){
                    __half2* Ch=(__half2*)C;
                    Ch[(size_t)r0*64+(n>>1)]=__floats2half2_rn(o0.x,o0.y);
                    Ch[(size_t)(r0+8)*64+(n>>1)]=__floats2half2_rn(o1.x,o1.y);
                }else{
                    float* Cf=(float*)C;
                    *(float2*)(Cf+(size_t)r0*128+n)=o0;
                    *(float2*)(Cf+(size_t)(r0+8)*128+n)=o1;
                }
            }
        }
        __syncthreads();
    }
}

// ---------------- attention: two-phase, register-prefetched, scalar geo ----------------
__device__ __forceinline__ float4 up4(uint2 u){
    float2 a=__half22float2(*(__half2*)&u.x), b=__half22float2(*(__half2*)&u.y);
    return make_float4(a.x,a.y,b.x,b.y);
}
__device__ __forceinline__ float wredu(float v){
#pragma unroll
    for(int o=16;o;o>>=1)v+=__shfl_xor_sync(0xffffffffu,v,o);
    return v;
}
__global__ void attn_k(const __half* __restrict__ Qh,const __half* __restrict__ FKh,
                       const __half* __restrict__ FVh,const float4* __restrict__ co,
                       float4* __restrict__ Out4,int layer){
    int n=(blockIdx.x*blockDim.x+threadIdx.x)>>5, ln=threadIdx.x&31;
    if(n>=Npts)return;
    const float4* Wk=(const float4*)(layer?d_Wpk1:d_Wpk0);
    const float4* Bk=(const float4*)(layer?d_bk1:d_bk0);
    float4 q=up4(((const uint2*)(Qh+(size_t)n*128))[ln]);
    float ax,ay,az,ab;
    {
        float4 wkx=Wk[ln],wky=Wk[32+ln],wkz=Wk[64+ln],bk=Bk[ln];
        ax=wredu(fmaf(wkx.w,q.w,fmaf(wkx.z,q.z,fmaf(wkx.y,q.y,wkx.x*q.x))));
        ay=wredu(fmaf(wky.w,q.w,fmaf(wky.z,q.z,fmaf(wky.y,q.y,wky.x*q.x))));
        az=wredu(fmaf(wkz.w,q.w,fmaf(wkz.z,q.z,fmaf(wkz.y,q.y,wkz.x*q.x))));
        ab=wredu(fmaf(bk.w,q.w,fmaf(bk.z,q.z,fmaf(bk.y,q.y,bk.x*q.x))));
    }
    float4 qc=co[n];
    int jj[KNN];
#pragma unroll
    for(int k=0;k<KNN;++k)jj[k]=d_knn[n*KNN+k];
    uint2 ur[KNN];
#pragma unroll
    for(int k=0;k<KNN;++k) ur[k]=((const uint2*)(FKh+(size_t)jj[k]*128))[ln];
    float sc[KNN];
#pragma unroll
    for(int k=0;k<KNN;++k){
        float4 fk=up4(ur[k]);
        float p=fmaf(fk.w,q.w,fmaf(fk.z,q.z,fmaf(fk.y,q.y,fk.x*q.x)));
#pragma unroll
        for(int o=16;o;o>>=1)p+=__shfl_xor_sync(0xffffffffu,p,o);
        float4 pj=co[jj[k]];
        float dx=qc.y-pj.y,dy=qc.z-pj.z,dz=qc.w-pj.w;
        sc[k]=(p+fmaf(dz,az,fmaf(dy,ay,fmaf(dx,ax,ab))))*0.08838834764831845f;
    }
#pragma unroll
    for(int k=0;k<KNN;++k) ur[k]=((const uint2*)(FVh+(size_t)jj[k]*128))[ln];
    float m=sc[0];
#pragma unroll
    for(int k=1;k<KNN;++k)m=fmaxf(m,sc[k]);
    float sum=0.f;
#pragma unroll
    for(int k=0;k<KNN;++k){ sc[k]=__expf(sc[k]-m); sum+=sc[k]; }
    float Sx=0.f,Sy=0.f,Sz=0.f;
    float4 ac=make_float4(0.f,0.f,0.f,0.f);
#pragma unroll
    for(int k=0;k<KNN;++k){
        float a=sc[k];
        float4 pj=co[jj[k]];
        float dx=qc.y-pj.y,dy=qc.z-pj.z,dz=qc.w-pj.w;
        Sx=fmaf(a,dx,Sx); Sy=fmaf(a,dy,Sy); Sz=fmaf(a,dz,Sz);
        float4 fv=up4(ur[k]);
        ac.x=fmaf(a,fv.x,ac.x); ac.y=fmaf(a,fv.y,ac.y);
        ac.z=fmaf(a,fv.z,ac.z); ac.w=fmaf(a,fv.w,ac.w);
    }
    const float4* Wv=(const float4*)(layer?d_Wpv1:d_Wpv0);
    const float4* Bv=(const float4*)(layer?d_bv1:d_bv0);
    float4 wvx=Wv[ln],wvy=Wv[32+ln],wvz=Wv[64+ln],bv=Bv[ln];
    float inv=1.f/sum;
    float sx=Sx*inv, sy=Sy*inv, sz=Sz*inv;
    float4 o;
    o.x=fmaf(ac.x,inv,fmaf(sx,wvx.x,fmaf(sy,wvy.x,fmaf(sz,wvz.x,bv.x))));
    o.y=fmaf(ac.y,inv,fmaf(sx,wvx.y,fmaf(sy,wvy.y,fmaf(sz,wvz.y,bv.y))));
    o.z=fmaf(ac.z,inv,fmaf(sx,wvx.z,fmaf(sy,wvy.z,fmaf(sz,wvz.z,bv.z))));
    o.w=fmaf(ac.w,inv,fmaf(sx,wvx.w,fmaf(sy,wvy.w,fmaf(sz,wvz.w,bv.w))));
    Out4[n*32+ln]=o;
}

__global__ void ln_k(const float4* __restrict__ X4,const float4* __restrict__ Y4,
                     const float4* __restrict__ g4,const float4* __restrict__ b4,
                     float4* __restrict__ out4){
    int n=(blockIdx.x*blockDim.x+threadIdx.x)>>5, ln=threadIdx.x&31;
    if(n>=Npts)return;
    float4 x=X4[n*32+ln], y=Y4[n*32+ln];
    float4 v; v.x=x.x+y.x; v.y=x.y+y.y; v.z=x.z+y.z; v.w=x.w+y.w;
    float s=v.x+v.y+v.z+v.w;
#pragma unroll
    for(int o=16;o;o>>=1)s+=__shfl_xor_sync(0xffffffffu,s,o);
    float mu=s*(1.f/128.f);
    float dx=v.x-mu,dy=v.y-mu,dz=v.z-mu,dw=v.w-mu;
    float vs=fmaf(dx,dx,fmaf(dy,dy,fmaf(dz,dz,dw*dw)));
#pragma unroll
    for(int o=16;o;o>>=1)vs+=__shfl_xor_sync(0xffffffffu,vs,o);
    float inv=rsqrtf(vs*(1.f/128.f)+128.f);
    float4 g=g4[ln],b=b4[ln],o;
    o.x=fmaf(dx*inv,g.x,b.x); o.y=fmaf(dy*inv,g.y,b.y);
    o.z=fmaf(dz*inv,g.z,b.z); o.w=fmaf(dw*inv,g.w,b.w);
    out4[n*32+ln]=o;
}

extern "C" void kernel_launch(void* const* d_in,const int* in_sizes,int n_in,
                              void* d_out,int out_size){
    const float4* co=(const float4*)d_in[0];
    const float* feats=(const float*)d_in[1];
    const float* pw=(const float*)d_in[2];  const float* pb=(const float*)d_in[3];
    const float* p1w=(const float*)d_in[4]; const float* p1b=(const float*)d_in[5];
    const float* qw0=(const float*)d_in[6]; const float* qb0=(const float*)d_in[7];
    const float* kw0=(const float*)d_in[8]; const float* kb0=(const float*)d_in[9];
    const float* vw0=(const float*)d_in[10];const float* vb0=(const float*)d_in[11];
    const float* qw1=(const float*)d_in[12];const float* qb1=(const float*)d_in[13];
    const float* kw1=(const float*)d_in[14];const float* kb1=(const float*)d_in[15];
    const float* vw1=(const float*)d_in[16];const float* vb1=(const float*)d_in[17];
    const float* lw=(const float*)d_in[18]; const float* lb=(const float*)d_in[19];
    const float* g0=(const float*)d_in[20]; const float* be0=(const float*)d_in[21];
    const float* g1=(const float*)d_in[22]; const float* be1=(const float*)d_in[23];
    float* out=(float*)d_out;

    __half *Q,*FK,*FV; float *O0,*O1,*H,*H1; unsigned short *WH;
    int *CC,*NF;
    cudaGetSymbolAddress((void**)&Q,d_Q);   cudaGetSymbolAddress((void**)&FK,d_FK);
    cudaGetSymbolAddress((void**)&FV,d_FV); cudaGetSymbolAddress((void**)&O0,d_O0);
    cudaGetSymbolAddress((void**)&O1,d_O1); cudaGetSymbolAddress((void**)&H,d_H);
    cudaGetSymbolAddress((void**)&H1,d_H1);
    cudaGetSymbolAddress((void**)&WH,d_wbh);
    cudaGetSymbolAddress((void**)&CC,d_cc); cudaGetSymbolAddress((void**)&NF,d_nflag);
    const float* nf=0;
    cudaFuncSetAttribute(gemmM_k,cudaFuncAttributeMaxDynamicSharedMemorySize,GM_SMEM);
#define WQ(i) (WH+(i)*16384)

    cudaMemsetAsync(CC,0,NCELL*sizeof(int),(cudaStream_t)0);
    cudaMemsetAsync(NF,0,sizeof(int),(cudaStream_t)0);
    hist_k<<<128,256>>>(co);
    scan_k<<<1,1024>>>();
    scat_k<<<128,256>>>(co);
    knn_k<<<128,512>>>();                    // profiled slot
    knn_fb<<<64,256>>>(co);
    prep_wb<<<112,256>>>(qw0,kw0,vw0,qw1,kw1,vw1,lw);
    gemmM_k<<<256,256,GM_SMEM>>>(feats,WQ(0),WQ(1),WQ(2),qb0,nf,nf,Q,FK,FV,3,1);
    prep_w<<<1,128>>>(pw,pb,p1w,p1b,kw0,kb0,vw0,vb0,kw1,kb1,vw1,vb1);
    attn_k<<<4096,256>>>(Q,FK,FV,co,(float4*)O0,0);
    gemmM_k<<<256,256,GM_SMEM>>>(O0,WQ(3),WQ(4),WQ(5),qb1,nf,nf,Q,FK,FV,3,1);
    attn_k<<<4096,256>>>(Q,FK,FV,co,(float4*)O1,1);
    ln_k<<<4096,256>>>((const float4*)feats,(const float4*)O1,(const float4*)g0,(const float4*)be0,(float4*)H);
    gemmM_k<<<256,256,GM_SMEM>>>(H,WQ(6),WQ(6),WQ(6),lb,nf,nf,H1,(float*)0,(float*)0,1,0);
    ln_k<<<4096,256>>>((const float4*)H,(const float4*)H1,(const float4*)g1,(const float4*)be1,(float4*)out);
}

// round 17
// speedup vs baseline: 1.5676x; 1.0757x over previous
#include <cuda_runtime.h>
#include <cuda_fp16.h>
#include <math.h>

#define Npts 32768
#define CCH 128
#define KNN 16
#define GDIM 20
#define NCELL 8000
#define CS 5.0f
#define CINV 0.2f
#define FLTMAX 3.402823466e38f

__device__ int    d_cc[NCELL];
__device__ int    d_cs[NCELL + 1];
__device__ int    d_cur[NCELL];
__device__ float4 d_sorted[Npts];
__device__ int    d_knn[Npts * KNN];
__device__ int    d_nflag;
__device__ int    d_flag[Npts];
__device__ __align__(16) float d_Wpk0[3*CCH], d_bk0[CCH], d_Wpv0[3*CCH], d_bv0[CCH];
__device__ __align__(16) float d_Wpk1[3*CCH], d_bk1[CCH], d_Wpv1[3*CCH], d_bv1[CCH];
__device__ __align__(16) __half d_Q[Npts*CCH], d_FK[Npts*CCH], d_FV[Npts*CCH];
__device__ float d_O0[Npts*CCH], d_O1[Npts*CCH], d_H[Npts*CCH], d_H1[Npts*CCH];
__device__ __align__(16) unsigned short d_wbh[7*16384];

__device__ __forceinline__ int cellof(float x){ int c=(int)(x*CINV); return min(GDIM-1,max(0,c)); }

#define CPA16(dst,src)  asm volatile("cp.async.cg.shared.global [%0],[%1],16;"::"r"(dst),"l"(src))
#define CPA_COMMIT()    asm volatile("cp.async.commit_group;")
#define CPA_WAIT(n)     asm volatile("cp.async.wait_group %0;"::"n"(n):"memory")
__device__ __forceinline__ unsigned s2u(const void* p){
    unsigned a; asm("{.reg .u64 t; cvta.to.shared.u64 t,%1; cvt.u32.u64 %0,t;}":"=r"(a):"l"(p)); return a; }
__device__ __forceinline__ void ldsm4(unsigned* r, unsigned addr){
    asm volatile("ldmatrix.sync.aligned.m8n8.x4.shared.b16 {%0,%1,%2,%3},[%4];"
        :"=r"(r[0]),"=r"(r[1]),"=r"(r[2]),"=r"(r[3]):"r"(addr));
}
__device__ __forceinline__ void mma16816h(float* d,const unsigned* a,unsigned b0,unsigned b1){
    asm volatile("mma.sync.aligned.m16n8k16.row.col.f32.f16.f16.f32 "
        "{%0,%1,%2,%3},{%4,%5,%6,%7},{%8,%9},{%0,%1,%2,%3};"
        :"+f"(d[0]),"+f"(d[1]),"+f"(d[2]),"+f"(d[3])
        :"r"(a[0]),"r"(a[1]),"r"(a[2]),"r"(a[3]),"r"(b0),"r"(b1));
}

// ---------------- grid build + knn ----------------
__global__ void hist_k(const float4* __restrict__ co){
    int i=blockIdx.x*256+threadIdx.x; if(i>=Npts)return; float4 c=co[i];
    atomicAdd(&d_cc[(cellof(c.w)*GDIM+cellof(c.z))*GDIM+cellof(c.y)],1);
}
__global__ void scan_k(){
    __shared__ int s[1024]; int t=threadIdx.x;
    int b=t*8, c[8], sum=0;
    if(t<1000){
#pragma unroll
        for(int i=0;i<8;++i){ c[i]=d_cc[b+i]; sum+=c[i]; }
    }
    s[t]=sum; __syncthreads();
    for(int o=1;o<1024;o<<=1){ int v=(t>=o)?s[t-o]:0; __syncthreads(); s[t]+=v; __syncthreads(); }
    int run=s[t]-sum;
    if(t<1000){
#pragma unroll
        for(int i=0;i<8;++i){ d_cs[b+i]=run; d_cur[b+i]=run; run+=c[i]; }
    }
    if(t==1023)d_cs[NCELL]=s[1023];
}
__global__ void scat_k(const float4* __restrict__ co){
    int i=blockIdx.x*256+threadIdx.x; if(i>=Npts)return; float4 c=co[i];
    int id=(cellof(c.w)*GDIM+cellof(c.z))*GDIM+cellof(c.y);
    d_sorted[atomicAdd(&d_cur[id],1)]=make_float4(c.y,c.z,c.w,__int_as_float(i));
}

__device__ __forceinline__ void ins1(float d,int idx,float(&ds)[KNN],int(&nb)[KNN]){
    if(d<ds[KNN-1]){ float cd=d; int ci=idx;
#pragma unroll
        for(int u=0;u<KNN;++u) if(cd<ds[u]){float td=ds[u];ds[u]=cd;cd=td;int ti=nb[u];nb[u]=ci;ci=ti;}
    }
}
__device__ __forceinline__ void seg(int s_,int e,int st,float qx,float qy,float qz,float(&ds)[KNN],int(&nb)[KNN]){
    int t=s_+st;
    for(; t+6<e; t+=8){
        float4 p0=d_sorted[t],p1=d_sorted[t+2],p2=d_sorted[t+4],p3=d_sorted[t+6];
        float x0=qx-p0.x,y0=qy-p0.y,z0=qz-p0.z; float d0=fmaf(x0,x0,fmaf(y0,y0,z0*z0));
        float x1=qx-p1.x,y1=qy-p1.y,z1=qz-p1.z; float d1=fmaf(x1,x1,fmaf(y1,y1,z1*z1));
        float x2=qx-p2.x,y2=qy-p2.y,z2=qz-p2.z; float d2=fmaf(x2,x2,fmaf(y2,y2,z2*z2));
        float x3=qx-p3.x,y3=qy-p3.y,z3=qz-p3.z; float d3=fmaf(x3,x3,fmaf(y3,y3,z3*z3));
        ins1(d0,__float_as_int(p0.w),ds,nb);
        ins1(d1,__float_as_int(p1.w),ds,nb);
        ins1(d2,__float_as_int(p2.w),ds,nb);
        ins1(d3,__float_as_int(p3.w),ds,nb);
    }
    for(;t<e;t+=2){ float4 p=d_sorted[t];
        float dx=qx-p.x,dy=qy-p.y,dz=qz-p.z;
        ins1(fmaf(dx,dx,fmaf(dy,dy,dz*dz)),__float_as_int(p.w),ds,nb);
    }
}
__global__ void knn_k(){
    int qt=blockIdx.x*512+threadIdx.x;
    int i=qt>>1, st=qt&1;
    if(i>=Npts)return;
    float4 q=d_sorted[i]; float qx=q.x,qy=q.y,qz=q.z; int qi=__float_as_int(q.w);
    int cx=cellof(qx),cy=cellof(qy),cz=cellof(qz);
    float ds[KNN]; int nb[KNN];
#pragma unroll
    for(int u=0;u<KNN;++u){ds[u]=FLTMAX;nb[u]=0;}
    int x0a=max(cx-1,0),x1a=min(cx+1,GDIM-1),y0a=max(cy-1,0),y1a=min(cy+1,GDIM-1),z0a=max(cz-1,0),z1a=min(cz+1,GDIM-1);
    int x0b=max(cx-2,0),x1b=min(cx+2,GDIM-1),y0b=max(cy-2,0),y1b=min(cy+2,GDIM-1),z0b=max(cz-2,0),z1b=min(cz+2,GDIM-1);
    for(int zz=z0a;zz<=z1a;++zz)for(int yy=y0a;yy<=y1a;++yy){
        int rb=(zz*GDIM+yy)*GDIM; seg(d_cs[rb+x0a],d_cs[rb+x1a+1],st,qx,qy,qz,ds,nb); }
    for(int zz=z0b;zz<=z1b;++zz){
        float tz=fmaxf(fmaxf(zz*CS-qz,qz-(zz+1)*CS),0.f);
        for(int yy=y0b;yy<=y1b;++yy){
            float ty=fmaxf(fmaxf(yy*CS-qy,qy-(yy+1)*CS),0.f); float tyz=ty*ty+tz*tz;
            int rb=(zz*GDIM+yy)*GDIM;
            bool inr=(zz>=z0a&&zz<=z1a&&yy>=y0a&&yy<=y1a);
            if(!inr){ if(tyz<ds[KNN-1]) seg(d_cs[rb+x0b],d_cs[rb+x1b+1],st,qx,qy,qz,ds,nb); }
            else{
                if(x0b<x0a){ float tx=qx-x0a*CS; if(tyz+tx*tx<ds[KNN-1]) seg(d_cs[rb+x0b],d_cs[rb+x0a],st,qx,qy,qz,ds,nb);}
                if(x1b>x1a){ float tx=(x1a+1)*CS-qx; if(tyz+tx*tx<ds[KNN-1]) seg(d_cs[rb+x1a+1],d_cs[rb+x1b+1],st,qx,qy,qz,ds,nb);}
            }
        }}
    float mx=0.f; int LI[KNN];
#pragma unroll
    for(int u=0;u<KNN;++u){
        float pv=__shfl_xor_sync(0xffffffffu,ds[KNN-1-u],1);
        int   pi=__shfl_xor_sync(0xffffffffu,nb[KNN-1-u],1);
        float lv; int li;
        if(ds[u]<=pv){lv=ds[u];li=nb[u];}else{lv=pv;li=pi;}
        mx=fmaxf(mx,lv); LI[u]=li;
    }
    if(st==0){
        float Rg=2.f*CS-0.01f;
        if(mx<=Rg*Rg){
#pragma unroll
            for(int u=0;u<KNN;++u)d_knn[qi*KNN+u]=LI[u];
        }else d_flag[atomicAdd(&d_nflag,1)]=qi;
    }
}
__global__ void knn_fb(const float4* __restrict__ co){
    __shared__ float sd[8][512]; __shared__ int si[8][512];
    int wl=threadIdx.x>>5,ln=threadIdx.x&31;
    int gw=blockIdx.x*8+wl, tot=gridDim.x*8, nf=d_nflag;
    for(int w=gw;w<nf;w+=tot){
        int qi=d_flag[w]; float4 qc=co[qi]; float qx=qc.y,qy=qc.z,qz=qc.w;
        float ds[KNN]; int nb[KNN];
#pragma unroll
        for(int u=0;u<KNN;++u){ds[u]=FLTMAX;nb[u]=0;}
        for(int t=ln;t<Npts;t+=32){ float4 p=co[t];
            float dx=qx-p.y,dy=qy-p.z,dz=qz-p.w;
            ins1(fmaf(dx,dx,fmaf(dy,dy,dz*dz)),t,ds,nb);
        }
#pragma unroll
        for(int u=0;u<KNN;++u){sd[wl][ln*16+u]=ds[u];si[wl][ln*16+u]=nb[u];}
        __syncwarp();
        if(ln==0) for(int r=0;r<KNN;++r){
            float bm=FLTMAX;int bp=0;
            for(int t=0;t<512;++t) if(sd[wl][t]<bm){bm=sd[wl][t];bp=t;}
            d_knn[qi*KNN+r]=si[wl][bp]; sd[wl][bp]=FLTMAX; }
        __syncwarp();
    }
}

__global__ void prep_w(const float* pw,const float* pb,const float* p1w,const float* p1b,
                       const float* kw0,const float* kb0,const float* vw0,const float* vb0,
                       const float* kw1,const float* kb1,const float* vw1,const float* vb1){
    int c=threadIdx.x;
    for(int m=0;m<3;++m){ float a=0,b=0,e=0,f=0;
        for(int t=0;t<CCH;++t){ a=fmaf(pw[m*CCH+t],kw0[t*CCH+c],a); b=fmaf(pw[m*CCH+t],vw0[t*CCH+c],b);
            e=fmaf(p1w[m*CCH+t],kw1[t*CCH+c],e); f=fmaf(p1w[m*CCH+t],vw1[t*CCH+c],f); }
        d_Wpk0[m*CCH+c]=a; d_Wpv0[m*CCH+c]=b; d_Wpk1[m*CCH+c]=e; d_Wpv1[m*CCH+c]=f; }
    float a=0,b=0,e=0,f=0;
    for(int t=0;t<CCH;++t){ a=fmaf(pb[t],kw0[t*CCH+c],a); b=fmaf(pb[t],vw0[t*CCH+c],b);
        e=fmaf(p1b[t],kw1[t*CCH+c],e); f=fmaf(p1b[t],vw1[t*CCH+c],f); }
    d_bk0[c]=a+kb0[c]; d_bv0[c]=b+vb0[c]; d_bk1[c]=e+kb1[c]; d_bv1[c]=f+vb1[c];
}

__global__ void prep_wb(const float* w0,const float* w1,const float* w2,const float* w3,
                        const float* w4,const float* w5,const float* w6){
    int m=blockIdx.x>>4;
    const float* W=(m==0)?w0:(m==1)?w1:(m==2)?w2:(m==3)?w3:(m==4)?w4:(m==5)?w5:w6;
    int q=(blockIdx.x&15)*256+threadIdx.x;
    int n=q>>5, k0=(q&31)*4;
    union{__half b[4]; unsigned long long u;} H;
#pragma unroll
    for(int i=0;i<4;++i) H.b[i]=__float2half_rn(W[(k0+i)*128+n]);
    *(unsigned long long*)((char*)d_wbh + m*32768 + n*256 + k0*2)=H.u;
}

// ---- fp16 HMMA GEMM ----
#define APAD 272
#define OFF_A  0
#define OFF_B0 (128*APAD)
#define OFF_B1 (2*128*APAD)
#define GM_SMEM (3*128*APAD)

__global__ void __launch_bounds__(256,2)
gemmM_k(const float* __restrict__ A,
        const unsigned short* __restrict__ wh0,const unsigned short* __restrict__ wh1,
        const unsigned short* __restrict__ wh2,
        const float* __restrict__ bi0,const float* __restrict__ bi1,const float* __restrict__ bi2,
        void* __restrict__ C0,void* __restrict__ C1,void* __restrict__ C2,int nmat,int h16){
    extern __shared__ __align__(16) char sm[];
    unsigned sb=s2u(sm);
    int tid=threadIdx.x, wid=tid>>5, lane=tid&31, row0=blockIdx.x*128;
    {
        const unsigned short* W=wh0;
        for(int i=tid;i<2048;i+=256){ int r=i>>4, ch=(i&15)*16;
            CPA16(sb+OFF_B0+r*APAD+ch,(const char*)W+r*256+ch); }
        CPA_COMMIT();
    }
    {
        int row=tid>>1, half=(tid&1)*64;
        const float4* Ar=(const float4*)(A+(size_t)(row0+row)*128+half);
        char* dh=sm+OFF_A+row*APAD+half*2;
#pragma unroll
        for(int c4=0;c4<16;++c4){
            float4 v=Ar[c4];
            union{__half b[4]; unsigned long long u;} H;
            H.b[0]=__float2half_rn(v.x); H.b[1]=__float2half_rn(v.y);
            H.b[2]=__float2half_rn(v.z); H.b[3]=__float2half_rn(v.w);
            *(unsigned long long*)(dh+c4*8)=H.u;
        }
    }
    int wm=wid>>1, wn=wid&1;
    unsigned arow=sb+OFF_A+(wm*32+(lane&15))*APAD+(lane>>4)*16;
    for(int m=0;m<nmat;++m){
        if(m+1<nmat){
            const unsigned short* W=(m+1==1)?wh1:wh2;
            unsigned bo=((m+1)&1)?OFF_B1:OFF_B0;
            for(int i=tid;i<2048;i+=256){ int r=i>>4, ch=(i&15)*16;
                CPA16(sb+bo+r*APAD+ch,(const char*)W+r*256+ch); }
            CPA_COMMIT();
            CPA_WAIT(1);
        }else CPA_WAIT(0);
        __syncthreads();

        const float* bi=(m==0)?bi0:((m==1)?bi1:bi2);
        void* C=(m==0)?C0:((m==1)?C1:C2);
        unsigned brow=sb+((m&1)?OFF_B1:OFF_B0)+(wn*64+(lane&15))*APAD+(lane>>4)*16;

        float acc[2][8][4];
#pragma unroll
        for(int mt=0;mt<2;++mt)
#pragma unroll
            for(int nt=0;nt<8;++nt)
#pragma unroll
                for(int e=0;e<4;++e)acc[mt][nt][e]=0.f;
#pragma unroll
        for(int ks=0;ks<8;++ks){
            unsigned a0[4],a1[4],bg[4][4];
            unsigned kof=ks*32;
            ldsm4(a0,arow+kof);
            ldsm4(a1,arow+16*APAD+kof);
#pragma unroll
            for(int g=0;g<4;++g) ldsm4(bg[g],brow+g*16*APAD+kof);
#pragma unroll
            for(int mt=0;mt<2;++mt){
                const unsigned* af=mt?a1:a0;
#pragma unroll
                for(int nt=0;nt<8;++nt)
                    mma16816h(acc[mt][nt],af,bg[nt>>1][nt&1],bg[nt>>1][(nt&1)+2]);
            }
        }
#pragma unroll
        for(int mt=0;mt<2;++mt){
            int r0=row0+wm*32+mt*16+(lane>>2);
#pragma unroll
            for(int nt=0;nt<8;++nt){
                int n=wn*64+nt*8+(lane&3)*2;
                float2 bb=make_float2(0.f,0.f);
                if(bi) bb=*(const float2*)(bi+n);
                float2 o0; o0.x=acc[mt][nt][0]+bb.x; o0.y=acc[mt][nt][1]+bb.y;
                float2 o1; o1.x=acc[mt][nt][2]+bb.x; o1.y=acc[mt][nt][3]+bb.y;
                if(h16){
                    __half2* Ch=(__half2*)C;
                    Ch[(size_t)r0*64+(n>>1)]=__floats2half2_rn(o0.x,o0.y);
                    Ch[(size_t)(r0+8)*64+(n>>1)]=__floats2half2_rn(o1.x,o1.y);
                }else{
                    float* Cf=(float*)C;
                    *(float2*)(Cf+(size_t)r0*128+n)=o0;
                    *(float2*)(Cf+(size_t)(r0+8)*128+n)=o1;
                }
            }
        }
        __syncthreads();
    }
}

// ---------------- attention: two-phase v3 (loop-local loads, reg-capped) ----------------
__device__ __forceinline__ float4 up4(uint2 u){
    float2 a=__half22float2(*(__half2*)&u.x), b=__half22float2(*(__half2*)&u.y);
    return make_float4(a.x,a.y,b.x,b.y);
}
__device__ __forceinline__ float wredu(float v){
#pragma unroll
    for(int o=16;o;o>>=1)v+=__shfl_xor_sync(0xffffffffu,v,o);
    return v;
}
__global__ void __launch_bounds__(256,2)
attn_k(const __half* __restrict__ Qh,const __half* __restrict__ FKh,
       const __half* __restrict__ FVh,const float4* __restrict__ co,
       float4* __restrict__ Out4,int layer){
    int n=(blockIdx.x*blockDim.x+threadIdx.x)>>5, ln=threadIdx.x&31;
    if(n>=Npts)return;
    const float4* Wk=(const float4*)(layer?d_Wpk1:d_Wpk0);
    const float4* Bk=(const float4*)(layer?d_bk1:d_bk0);
    float4 q=up4(((const uint2*)(Qh+(size_t)n*128))[ln]);
    float ax,ay,az,ab;
    {
        float4 wkx=Wk[ln],wky=Wk[32+ln],wkz=Wk[64+ln],bk=Bk[ln];
        ax=wredu(fmaf(wkx.w,q.w,fmaf(wkx.z,q.z,fmaf(wkx.y,q.y,wkx.x*q.x))));
        ay=wredu(fmaf(wky.w,q.w,fmaf(wky.z,q.z,fmaf(wky.y,q.y,wky.x*q.x))));
        az=wredu(fmaf(wkz.w,q.w,fmaf(wkz.z,q.z,fmaf(wkz.y,q.y,wkz.x*q.x))));
        ab=wredu(fmaf(bk.w,q.w,fmaf(bk.z,q.z,fmaf(bk.y,q.y,bk.x*q.x))));
    }
    float4 qc=co[n];
    int jj[KNN];
#pragma unroll
    for(int k=0;k<KNN;++k)jj[k]=d_knn[n*KNN+k];
    // Phase A: scores with independent (pipelined) reduces; loads loop-local
    float sc[KNN];
#pragma unroll
    for(int k=0;k<KNN;++k){
        uint2 uk=((const uint2*)(FKh+(size_t)jj[k]*128))[ln];
        float4 fk=up4(uk);
        float p=fmaf(fk.w,q.w,fmaf(fk.z,q.z,fmaf(fk.y,q.y,fk.x*q.x)));
#pragma unroll
        for(int o=16;o;o>>=1)p+=__shfl_xor_sync(0xffffffffu,p,o);
        float4 pj=co[jj[k]];
        float dx=qc.y-pj.y,dy=qc.z-pj.z,dz=qc.w-pj.w;
        sc[k]=(p+fmaf(dz,az,fmaf(dy,ay,fmaf(dx,ax,ab))))*0.08838834764831845f;
    }
    float m=sc[0];
#pragma unroll
    for(int k=1;k<KNN;++k)m=fmaxf(m,sc[k]);
    float sum=0.f;
#pragma unroll
    for(int k=0;k<KNN;++k){ sc[k]=__expf(sc[k]-m); sum+=sc[k]; }
    // Phase B: weighted accumulation; loads loop-local
    float Sx=0.f,Sy=0.f,Sz=0.f;
    float4 ac=make_float4(0.f,0.f,0.f,0.f);
#pragma unroll
    for(int k=0;k<KNN;++k){
        float a=sc[k];
        uint2 uv=((const uint2*)(FVh+(size_t)jj[k]*128))[ln];
        float4 pj=co[jj[k]];
        float dx=qc.y-pj.y,dy=qc.z-pj.z,dz=qc.w-pj.w;
        Sx=fmaf(a,dx,Sx); Sy=fmaf(a,dy,Sy); Sz=fmaf(a,dz,Sz);
        float4 fv=up4(uv);
        ac.x=fmaf(a,fv.x,ac.x); ac.y=fmaf(a,fv.y,ac.y);
        ac.z=fmaf(a,fv.z,ac.z); ac.w=fmaf(a,fv.w,ac.w);
    }
    const float4* Wv=(const float4*)(layer?d_Wpv1:d_Wpv0);
    const float4* Bv=(const float4*)(layer?d_bv1:d_bv0);
    float4 wvx=Wv[ln],wvy=Wv[32+ln],wvz=Wv[64+ln],bv=Bv[ln];
    float inv=1.f/sum;
    float sx=Sx*inv, sy=Sy*inv, sz=Sz*inv;
    float4 o;
    o.x=fmaf(ac.x,inv,fmaf(sx,wvx.x,fmaf(sy,wvy.x,fmaf(sz,wvz.x,bv.x))));
    o.y=fmaf(ac.y,inv,fmaf(sx,wvx.y,fmaf(sy,wvy.y,fmaf(sz,wvz.y,bv.y))));
    o.z=fmaf(ac.z,inv,fmaf(sx,wvx.z,fmaf(sy,wvy.z,fmaf(sz,wvz.z,bv.z))));
    o.w=fmaf(ac.w,inv,fmaf(sx,wvx.w,fmaf(sy,wvy.w,fmaf(sz,wvz.w,bv.w))));
    Out4[n*32+ln]=o;
}

__global__ void ln_k(const float4* __restrict__ X4,const float4* __restrict__ Y4,
                     const float4* __restrict__ g4,const float4* __restrict__ b4,
                     float4* __restrict__ out4){
    int n=(blockIdx.x*blockDim.x+threadIdx.x)>>5, ln=threadIdx.x&31;
    if(n>=Npts)return;
    float4 x=X4[n*32+ln], y=Y4[n*32+ln];
    float4 v; v.x=x.x+y.x; v.y=x.y+y.y; v.z=x.z+y.z; v.w=x.w+y.w;
    float s=v.x+v.y+v.z+v.w;
#pragma unroll
    for(int o=16;o;o>>=1)s+=__shfl_xor_sync(0xffffffffu,s,o);
    float mu=s*(1.f/128.f);
    float dx=v.x-mu,dy=v.y-mu,dz=v.z-mu,dw=v.w-mu;
    float vs=fmaf(dx,dx,fmaf(dy,dy,fmaf(dz,dz,dw*dw)));
#pragma unroll
    for(int o=16;o;o>>=1)vs+=__shfl_xor_sync(0xffffffffu,vs,o);
    float inv=rsqrtf(vs*(1.f/128.f)+128.f);
    float4 g=g4[ln],b=b4[ln],o;
    o.x=fmaf(dx*inv,g.x,b.x); o.y=fmaf(dy*inv,g.y,b.y);
    o.z=fmaf(dz*inv,g.z,b.z); o.w=fmaf(dw*inv,g.w,b.w);
    out4[n*32+ln]=o;
}

extern "C" void kernel_launch(void* const* d_in,const int* in_sizes,int n_in,
                              void* d_out,int out_size){
    const float4* co=(const float4*)d_in[0];
    const float* feats=(const float*)d_in[1];
    const float* pw=(const float*)d_in[2];  const float* pb=(const float*)d_in[3];
    const float* p1w=(const float*)d_in[4]; const float* p1b=(const float*)d_in[5];
    const float* qw0=(const float*)d_in[6]; const float* qb0=(const float*)d_in[7];
    const float* kw0=(const float*)d_in[8]; const float* kb0=(const float*)d_in[9];
    const float* vw0=(const float*)d_in[10];const float* vb0=(const float*)d_in[11];
    const float* qw1=(const float*)d_in[12];const float* qb1=(const float*)d_in[13];
    const float* kw1=(const float*)d_in[14];const float* kb1=(const float*)d_in[15];
    const float* vw1=(const float*)d_in[16];const float* vb1=(const float*)d_in[17];
    const float* lw=(const float*)d_in[18]; const float* lb=(const float*)d_in[19];
    const float* g0=(const float*)d_in[20]; const float* be0=(const float*)d_in[21];
    const float* g1=(const float*)d_in[22]; const float* be1=(const float*)d_in[23];
    float* out=(float*)d_out;

    __half *Q,*FK,*FV; float *O0,*O1,*H,*H1; unsigned short *WH;
    int *CC,*NF;
    cudaGetSymbolAddress((void**)&Q,d_Q);   cudaGetSymbolAddress((void**)&FK,d_FK);
    cudaGetSymbolAddress((void**)&FV,d_FV); cudaGetSymbolAddress((void**)&O0,d_O0);
    cudaGetSymbolAddress((void**)&O1,d_O1); cudaGetSymbolAddress((void**)&H,d_H);
    cudaGetSymbolAddress((void**)&H1,d_H1);
    cudaGetSymbolAddress((void**)&WH,d_wbh);
    cudaGetSymbolAddress((void**)&CC,d_cc); cudaGetSymbolAddress((void**)&NF,d_nflag);
    const float* nf=0;
    cudaFuncSetAttribute(gemmM_k,cudaFuncAttributeMaxDynamicSharedMemorySize,GM_SMEM);
#define WQ(i) (WH+(i)*16384)

    cudaMemsetAsync(CC,0,NCELL*sizeof(int),(cudaStream_t)0);
    cudaMemsetAsync(NF,0,sizeof(int),(cudaStream_t)0);
    hist_k<<<128,256>>>(co);
    scan_k<<<1,1024>>>();
    scat_k<<<128,256>>>(co);
    knn_k<<<128,512>>>();                    // profiled slot (clock control)
    knn_fb<<<64,256>>>(co);
    prep_wb<<<112,256>>>(qw0,kw0,vw0,qw1,kw1,vw1,lw);
    gemmM_k<<<256,256,GM_SMEM>>>(feats,WQ(0),WQ(1),WQ(2),qb0,nf,nf,Q,FK,FV,3,1);
    prep_w<<<1,128>>>(pw,pb,p1w,p1b,kw0,kb0,vw0,vb0,kw1,kb1,vw1,vb1);
    attn_k<<<4096,256>>>(Q,FK,FV,co,(float4*)O0,0);
    gemmM_k<<<256,256,GM_SMEM>>>(O0,WQ(3),WQ(4),WQ(5),qb1,nf,nf,Q,FK,FV,3,1);
    attn_k<<<4096,256>>>(Q,FK,FV,co,(float4*)O1,1);
    ln_k<<<4096,256>>>((const float4*)feats,(const float4*)O1,(const float4*)g0,(const float4*)be0,(float4*)H);
    gemmM_k<<<256,256,GM_SMEM>>>(H,WQ(6),WQ(6),WQ(6),lb,nf,nf,H1,(float*)0,(float*)0,1,0);
    ln_k<<<4096,256>>>((const float4*)H,(const float4*)H1,(const float4*)g1,(const float4*)be1,(float4*)out);
}